// round 1
// baseline (speedup 1.0000x reference)
#include <cuda_runtime.h>
#include <cstdint>
#include <cstddef>

#define B_  4
#define S_  2048
#define D_  1024
#define H_  16
#define DK_ 64
#define BH_ (B_ * H_)

// Scratch (allocation-free rule: __device__ globals). 32MB each.
__device__ float g_Q[B_ * H_ * S_ * DK_];
__device__ float g_K[B_ * H_ * S_ * DK_];
__device__ float g_V[B_ * H_ * S_ * DK_];
__device__ float g_O[B_ * S_ * D_];

// ---------------------------------------------------------------------------
// Kernel 1: per-head QKV projection.
// x viewed as [B,S,H,DK]; Q[b,s,h,e] = sum_k x[b,s,h,k] * W[h,k,e] + b[h,e]
// Output layout: [B,H,S,DK] (attention-friendly).
// Grid: (B*S/64, H), 256 threads. smem: x tile (64x64, stride 65) + one W.
// ---------------------------------------------------------------------------
__global__ __launch_bounds__(256) void qkv_proj_kernel(
    const float* __restrict__ x,
    const float* __restrict__ Wq, const float* __restrict__ bq,
    const float* __restrict__ Wk, const float* __restrict__ bk,
    const float* __restrict__ Wv, const float* __restrict__ bv)
{
    __shared__ float xs[64 * 65];
    __shared__ float ws[64 * 64];

    const int h   = blockIdx.y;
    const int m0  = blockIdx.x * 64;          // global row (b*S + s) base
    const int tid = threadIdx.x;

    // Load x tile: 64 rows x 64 cols (this head's slice), float4 global reads.
    for (int i = tid; i < 1024; i += 256) {
        int r = i >> 4, c = (i & 15) << 2;
        float4 v = *reinterpret_cast<const float4*>(
            x + (size_t)(m0 + r) * D_ + h * DK_ + c);
        float* d = xs + r * 65 + c;
        d[0] = v.x; d[1] = v.y; d[2] = v.z; d[3] = v.w;
    }

    const float* Ws[3] = {Wq, Wk, Wv};
    const float* Bs[3] = {bq, bk, bv};
    float*       Ds[3] = {g_Q, g_K, g_V};

    const int ty = tid >> 4;        // 0..15 (row group)
    const int tx = tid & 15;        // 0..15 (col group)
    const int b  = m0 >> 11;        // m0 / S_
    const int s0 = m0 & (S_ - 1);

    for (int p = 0; p < 3; ++p) {
        const float4* wsrc = reinterpret_cast<const float4*>(Ws[p] + h * DK_ * DK_);
        for (int i = tid; i < 1024; i += 256)
            reinterpret_cast<float4*>(ws)[i] = wsrc[i];
        __syncthreads();

        float acc[4][4] = {};
        #pragma unroll 4
        for (int k = 0; k < 64; ++k) {
            float xv[4], wv[4];
            #pragma unroll
            for (int i = 0; i < 4; ++i) xv[i] = xs[(ty + 16 * i) * 65 + k];
            #pragma unroll
            for (int j = 0; j < 4; ++j) wv[j] = ws[k * 64 + tx + 16 * j];
            #pragma unroll
            for (int i = 0; i < 4; ++i)
                #pragma unroll
                for (int j = 0; j < 4; ++j)
                    acc[i][j] = fmaf(xv[i], wv[j], acc[i][j]);
        }

        float* dst = Ds[p] + ((size_t)(b * H_ + h) * S_ + s0) * DK_;
        const float* bias = Bs[p] + h * DK_;
        #pragma unroll
        for (int i = 0; i < 4; ++i) {
            int r = ty + 16 * i;
            #pragma unroll
            for (int j = 0; j < 4; ++j) {
                int e = tx + 16 * j;
                dst[(size_t)r * DK_ + e] = acc[i][j] + bias[e];
            }
        }
        __syncthreads();
    }
}

// ---------------------------------------------------------------------------
// Kernel 2: causal flash attention, BM=BN=64, one CTA per (q-tile, b*h).
// 128 threads: ty = tid>>3 (16 row groups), tx = tid&7 (8 col groups).
// Thread micro-tile: rows ty+16i (i<4), cols tx+8j (j<8).
// smem (dynamic, 49664B): Q [64x64 +pad65], K/P [64x64 +pad65], V [64x64].
// All inner-loop LDS are bank-conflict-free with zero extra address math.
// ---------------------------------------------------------------------------
__global__ __launch_bounds__(128, 4) void attn_kernel()
{
    extern __shared__ float smx[];
    float* qs  = smx;                 // 64*65
    float* kps = smx + 64 * 65;       // 64*65 (K, then reused for P)
    float* vs  = smx + 2 * 64 * 65;   // 64*64

    const int it  = (gridDim.x - 1) - blockIdx.x;   // heavy tiles first
    const int bh  = blockIdx.y;
    const int tid = threadIdx.x;
    const int ty  = tid >> 3;   // 0..15
    const int tx  = tid & 7;    // 0..7

    // Load Q tile (stays for the whole CTA).
    const float* Qp = g_Q + ((size_t)bh * S_ + it * 64) * DK_;
    for (int i = tid; i < 1024; i += 128) {
        int r = i >> 4, c = (i & 15) << 2;
        float4 v = *reinterpret_cast<const float4*>(Qp + r * 64 + c);
        float* d = qs + r * 65 + c;
        d[0] = v.x; d[1] = v.y; d[2] = v.z; d[3] = v.w;
    }

    float m_r[4], l_r[4], o[4][8];
    #pragma unroll
    for (int i = 0; i < 4; ++i) {
        m_r[i] = -1e30f; l_r[i] = 0.f;
        #pragma unroll
        for (int j = 0; j < 8; ++j) o[i][j] = 0.f;
    }

    const float SCL = 0.18033688011112042f;  // log2(e) / sqrt(DK)

    for (int jt = 0; jt <= it; ++jt) {
        __syncthreads();  // prev PV reads done (also covers Q load at jt=0)

        const float* Kp = g_K + ((size_t)bh * S_ + jt * 64) * DK_;
        const float* Vp = g_V + ((size_t)bh * S_ + jt * 64) * DK_;
        for (int i = tid; i < 1024; i += 128) {
            int r = i >> 4, c = (i & 15) << 2;
            float4 kv = *reinterpret_cast<const float4*>(Kp + r * 64 + c);
            float* d = kps + r * 65 + c;
            d[0] = kv.x; d[1] = kv.y; d[2] = kv.z; d[3] = kv.w;
            *reinterpret_cast<float4*>(vs + r * 64 + c) =
                *reinterpret_cast<const float4*>(Vp + r * 64 + c);
        }
        __syncthreads();

        // S = Q K^T  (4x8 micro-tile per thread)
        float s[4][8];
        #pragma unroll
        for (int i = 0; i < 4; ++i)
            #pragma unroll
            for (int j = 0; j < 8; ++j) s[i][j] = 0.f;

        #pragma unroll 4
        for (int k = 0; k < 64; ++k) {
            float a[4], bb[8];
            #pragma unroll
            for (int i = 0; i < 4; ++i) a[i] = qs[(ty + 16 * i) * 65 + k];
            #pragma unroll
            for (int j = 0; j < 8; ++j) bb[j] = kps[(tx + 8 * j) * 65 + k];
            #pragma unroll
            for (int i = 0; i < 4; ++i)
                #pragma unroll
                for (int j = 0; j < 8; ++j)
                    s[i][j] = fmaf(a[i], bb[j], s[i][j]);
        }

        // Online softmax (log2 domain).
        const bool diag = (jt == it);
        #pragma unroll
        for (int i = 0; i < 4; ++i) {
            const int r = ty + 16 * i;
            float rm = -1e30f;
            #pragma unroll
            for (int j = 0; j < 8; ++j) {
                float v = s[i][j] * SCL;
                if (diag && (tx + 8 * j) > r) v = -1e30f;   // causal mask
                s[i][j] = v;
                rm = fmaxf(rm, v);
            }
            rm = fmaxf(rm, __shfl_xor_sync(0xffffffffu, rm, 1));
            rm = fmaxf(rm, __shfl_xor_sync(0xffffffffu, rm, 2));
            rm = fmaxf(rm, __shfl_xor_sync(0xffffffffu, rm, 4));
            float mn    = fmaxf(m_r[i], rm);
            float alpha = exp2f(m_r[i] - mn);
            m_r[i] = mn;
            float rs = 0.f;
            #pragma unroll
            for (int j = 0; j < 8; ++j) {
                float p = exp2f(s[i][j] - mn);
                s[i][j] = p;
                rs += p;
            }
            rs += __shfl_xor_sync(0xffffffffu, rs, 1);
            rs += __shfl_xor_sync(0xffffffffu, rs, 2);
            rs += __shfl_xor_sync(0xffffffffu, rs, 4);
            l_r[i] = l_r[i] * alpha + rs;
            #pragma unroll
            for (int j = 0; j < 8; ++j) o[i][j] *= alpha;
        }

        // Stage P into smem (reuse K buffer), then O += P V.
        __syncthreads();   // all K reads finished
        #pragma unroll
        for (int i = 0; i < 4; ++i)
            #pragma unroll
            for (int j = 0; j < 8; ++j)
                kps[(ty + 16 * i) * 65 + tx + 8 * j] = s[i][j];
        __syncthreads();

        #pragma unroll 4
        for (int jj = 0; jj < 64; ++jj) {
            float pv[4], vv[8];
            #pragma unroll
            for (int i = 0; i < 4; ++i) pv[i] = kps[(ty + 16 * i) * 65 + jj];
            #pragma unroll
            for (int j = 0; j < 8; ++j) vv[j] = vs[jj * 64 + tx + 8 * j];
            #pragma unroll
            for (int i = 0; i < 4; ++i)
                #pragma unroll
                for (int j = 0; j < 8; ++j)
                    o[i][j] = fmaf(pv[i], vv[j], o[i][j]);
        }
    }

    // Epilogue: normalize, write O in [B,S,D] layout (heads concatenated).
    const int b = bh >> 4, h = bh & 15;
    #pragma unroll
    for (int i = 0; i < 4; ++i) {
        float inv = 1.0f / l_r[i];
        int srow  = it * 64 + ty + 16 * i;
        float* dst = g_O + ((size_t)(b * S_ + srow)) * D_ + h * DK_;
        #pragma unroll
        for (int j = 0; j < 8; ++j) dst[tx + 8 * j] = o[i][j] * inv;
    }
}

// ---------------------------------------------------------------------------
// Kernel 3: residual + LayerNorm. One CTA (256 thr) per (b,s) row, D=1024.
// ---------------------------------------------------------------------------
__global__ __launch_bounds__(256) void ln_res_kernel(
    const float* __restrict__ x,
    const float* __restrict__ gamma,
    const float* __restrict__ beta,
    float* __restrict__ out)
{
    const int row = blockIdx.x;
    const int tid = threadIdx.x;

    float4 ov = reinterpret_cast<const float4*>(g_O + (size_t)row * D_)[tid];
    float4 xv = reinterpret_cast<const float4*>(x   + (size_t)row * D_)[tid];
    float4 y;
    y.x = ov.x + xv.x; y.y = ov.y + xv.y; y.z = ov.z + xv.z; y.w = ov.w + xv.w;

    float s  = y.x + y.y + y.z + y.w;
    float ss = y.x * y.x + y.y * y.y + y.z * y.z + y.w * y.w;
    #pragma unroll
    for (int off = 16; off; off >>= 1) {
        s  += __shfl_xor_sync(0xffffffffu, s,  off);
        ss += __shfl_xor_sync(0xffffffffu, ss, off);
    }

    __shared__ float red[16];
    __shared__ float mu_s, rs_s;
    const int wid = tid >> 5;
    if ((tid & 31) == 0) { red[wid] = s; red[wid + 8] = ss; }
    __syncthreads();
    if (tid == 0) {
        float S = 0.f, SS = 0.f;
        #pragma unroll
        for (int i = 0; i < 8; ++i) { S += red[i]; SS += red[i + 8]; }
        float mu  = S * (1.0f / D_);
        float var = SS * (1.0f / D_) - mu * mu;
        mu_s = mu;
        rs_s = rsqrtf(var + 1e-5f);
    }
    __syncthreads();

    const float mu = mu_s, rstd = rs_s;
    float4 gv = reinterpret_cast<const float4*>(gamma)[tid];
    float4 bv = reinterpret_cast<const float4*>(beta)[tid];
    float4 r;
    r.x = (y.x - mu) * rstd * gv.x + bv.x;
    r.y = (y.y - mu) * rstd * gv.y + bv.y;
    r.z = (y.z - mu) * rstd * gv.z + bv.z;
    r.w = (y.w - mu) * rstd * gv.w + bv.w;
    reinterpret_cast<float4*>(out + (size_t)row * D_)[tid] = r;
}

// ---------------------------------------------------------------------------
extern "C" void kernel_launch(void* const* d_in, const int* in_sizes, int n_in,
                              void* d_out, int out_size)
{
    const float* x     = (const float*)d_in[0];
    const float* Wq    = (const float*)d_in[1];
    const float* bq    = (const float*)d_in[2];
    const float* Wk    = (const float*)d_in[3];
    const float* bk    = (const float*)d_in[4];
    const float* Wv    = (const float*)d_in[5];
    const float* bv    = (const float*)d_in[6];
    const float* gamma = (const float*)d_in[7];
    const float* beta  = (const float*)d_in[8];
    float* out = (float*)d_out;

    const int ATTN_SMEM = (2 * 64 * 65 + 64 * 64) * (int)sizeof(float); // 49664
    // Not a stream op; already effective from the (uncaptured) correctness call.
    cudaFuncSetAttribute(attn_kernel,
                         cudaFuncAttributeMaxDynamicSharedMemorySize, ATTN_SMEM);

    qkv_proj_kernel<<<dim3((B_ * S_) / 64, H_), 256>>>(x, Wq, bq, Wk, bk, Wv, bv);
    attn_kernel<<<dim3(S_ / 64, BH_), 128, ATTN_SMEM>>>();
    ln_res_kernel<<<B_ * S_, 256>>>(x, gamma, beta, out);
}

// round 2
// speedup vs baseline: 2.6191x; 2.6191x over previous
#include <cuda_runtime.h>
#include <cstdint>
#include <cstddef>

#define B_  4
#define S_  2048
#define D_  1024
#define H_  16
#define DK_ 64
#define BH_ (B_ * H_)

// Scratch (allocation-free rule: __device__ globals). 32MB each.
__device__ float g_Q[B_ * H_ * S_ * DK_];
__device__ float g_K[B_ * H_ * S_ * DK_];
__device__ float g_V[B_ * H_ * S_ * DK_];
__device__ float g_O[B_ * S_ * D_];

__device__ __forceinline__ uint32_t f2tf32(float x) {
    uint32_t u;
    asm("cvt.rna.tf32.f32 %0, %1;" : "=r"(u) : "f"(x));
    return u;
}

__device__ __forceinline__ void mma_tf32(float* c,
                                         uint32_t a0, uint32_t a1,
                                         uint32_t a2, uint32_t a3,
                                         uint32_t b0, uint32_t b1) {
    asm volatile(
        "mma.sync.aligned.m16n8k8.row.col.f32.tf32.tf32.f32 "
        "{%0,%1,%2,%3}, {%4,%5,%6,%7}, {%8,%9}, {%0,%1,%2,%3};"
        : "+f"(c[0]), "+f"(c[1]), "+f"(c[2]), "+f"(c[3])
        : "r"(a0), "r"(a1), "r"(a2), "r"(a3), "r"(b0), "r"(b1));
}

// ---------------------------------------------------------------------------
// Kernel 1: per-head QKV projection (FFMA; 113us, revisit after attention).
// ---------------------------------------------------------------------------
__global__ __launch_bounds__(256) void qkv_proj_kernel(
    const float* __restrict__ x,
    const float* __restrict__ Wq, const float* __restrict__ bq,
    const float* __restrict__ Wk, const float* __restrict__ bk,
    const float* __restrict__ Wv, const float* __restrict__ bv)
{
    __shared__ float xs[64 * 65];
    __shared__ float ws[64 * 64];

    const int h   = blockIdx.y;
    const int m0  = blockIdx.x * 64;
    const int tid = threadIdx.x;

    for (int i = tid; i < 1024; i += 256) {
        int r = i >> 4, c = (i & 15) << 2;
        float4 v = *reinterpret_cast<const float4*>(
            x + (size_t)(m0 + r) * D_ + h * DK_ + c);
        float* d = xs + r * 65 + c;
        d[0] = v.x; d[1] = v.y; d[2] = v.z; d[3] = v.w;
    }

    const float* Ws[3] = {Wq, Wk, Wv};
    const float* Bs[3] = {bq, bk, bv};
    float*       Ds[3] = {g_Q, g_K, g_V};

    const int ty = tid >> 4;
    const int tx = tid & 15;
    const int b  = m0 >> 11;
    const int s0 = m0 & (S_ - 1);

    for (int p = 0; p < 3; ++p) {
        const float4* wsrc = reinterpret_cast<const float4*>(Ws[p] + h * DK_ * DK_);
        for (int i = tid; i < 1024; i += 256)
            reinterpret_cast<float4*>(ws)[i] = wsrc[i];
        __syncthreads();

        float acc[4][4] = {};
        #pragma unroll 4
        for (int k = 0; k < 64; ++k) {
            float xv[4], wv[4];
            #pragma unroll
            for (int i = 0; i < 4; ++i) xv[i] = xs[(ty + 16 * i) * 65 + k];
            #pragma unroll
            for (int j = 0; j < 4; ++j) wv[j] = ws[k * 64 + tx + 16 * j];
            #pragma unroll
            for (int i = 0; i < 4; ++i)
                #pragma unroll
                for (int j = 0; j < 4; ++j)
                    acc[i][j] = fmaf(xv[i], wv[j], acc[i][j]);
        }

        float* dst = Ds[p] + ((size_t)(b * H_ + h) * S_ + s0) * DK_;
        const float* bias = Bs[p] + h * DK_;
        #pragma unroll
        for (int i = 0; i < 4; ++i) {
            int r = ty + 16 * i;
            #pragma unroll
            for (int j = 0; j < 4; ++j) {
                int e = tx + 16 * j;
                dst[(size_t)r * DK_ + e] = acc[i][j] + bias[e];
            }
        }
        __syncthreads();
    }
}

// ---------------------------------------------------------------------------
// Kernel 2: causal flash attention with tf32 mma.sync (m16n8k8).
// BM=BN=64, 128 threads (4 warps x 16 Q-rows). Per warp: 8 n-tiles.
// smem strides: Q/K/P = 68 (fragment bank = 4g+t, conflict-free),
//               V = 72 (fragment bank = 8t+g, conflict-free).
// ---------------------------------------------------------------------------
#define QS_ 68
#define VS_ 72

__global__ __launch_bounds__(128) void attn_kernel()
{
    extern __shared__ float smx[];
    float* qs  = smx;                 // 64*68  (Q, tf32)
    float* kps = smx + 64 * QS_;      // 64*68  (K, then reused for P)
    float* vs  = smx + 2 * 64 * QS_;  // 64*72  (V, tf32)

    const int it   = (gridDim.x - 1) - blockIdx.x;   // heavy tiles first
    const int bh   = blockIdx.y;
    const int tid  = threadIdx.x;
    const int lane = tid & 31;
    const int warp = tid >> 5;
    const int wrow = warp * 16;
    const int g    = lane >> 2;   // group id (0..7)
    const int t    = lane & 3;    // thread-in-group (0..3)

    // Stage Q (tf32) — stays for the whole CTA.
    const float* Qp = g_Q + ((size_t)bh * S_ + it * 64) * DK_;
    for (int i = tid; i < 1024; i += 128) {
        int r = i >> 4, c = (i & 15) << 2;
        float4 v = *reinterpret_cast<const float4*>(Qp + r * 64 + c);
        v.x = __uint_as_float(f2tf32(v.x));
        v.y = __uint_as_float(f2tf32(v.y));
        v.z = __uint_as_float(f2tf32(v.z));
        v.w = __uint_as_float(f2tf32(v.w));
        *reinterpret_cast<float4*>(qs + r * QS_ + c) = v;
    }

    float m0 = -1e30f, m1 = -1e30f, l0 = 0.f, l1 = 0.f;
    float oacc[8][4];
    #pragma unroll
    for (int et = 0; et < 8; ++et)
        #pragma unroll
        for (int q = 0; q < 4; ++q) oacc[et][q] = 0.f;

    const float SCL = 0.18033688011112042f;  // log2(e) / sqrt(DK)
    const int r0 = wrow + g, r1 = r0 + 8;

    for (int jt = 0; jt <= it; ++jt) {
        __syncthreads();  // prior PV reads / Q staging complete

        const float* Kp = g_K + ((size_t)bh * S_ + jt * 64) * DK_;
        const float* Vp = g_V + ((size_t)bh * S_ + jt * 64) * DK_;
        for (int i = tid; i < 1024; i += 128) {
            int r = i >> 4, c = (i & 15) << 2;
            float4 kv = *reinterpret_cast<const float4*>(Kp + r * 64 + c);
            kv.x = __uint_as_float(f2tf32(kv.x));
            kv.y = __uint_as_float(f2tf32(kv.y));
            kv.z = __uint_as_float(f2tf32(kv.z));
            kv.w = __uint_as_float(f2tf32(kv.w));
            *reinterpret_cast<float4*>(kps + r * QS_ + c) = kv;
            float4 vv = *reinterpret_cast<const float4*>(Vp + r * 64 + c);
            vv.x = __uint_as_float(f2tf32(vv.x));
            vv.y = __uint_as_float(f2tf32(vv.y));
            vv.z = __uint_as_float(f2tf32(vv.z));
            vv.w = __uint_as_float(f2tf32(vv.w));
            *reinterpret_cast<float4*>(vs + r * VS_ + c) = vv;
        }
        __syncthreads();

        // ---- S = Q K^T via tf32 mma ----
        float sacc[8][4];
        #pragma unroll
        for (int nt = 0; nt < 8; ++nt)
            #pragma unroll
            for (int q = 0; q < 4; ++q) sacc[nt][q] = 0.f;

        #pragma unroll
        for (int k0 = 0; k0 < 8; ++k0) {
            const int k = k0 * 8 + t;
            uint32_t a0 = __float_as_uint(qs[r0 * QS_ + k]);
            uint32_t a1 = __float_as_uint(qs[r1 * QS_ + k]);
            uint32_t a2 = __float_as_uint(qs[r0 * QS_ + k + 4]);
            uint32_t a3 = __float_as_uint(qs[r1 * QS_ + k + 4]);
            #pragma unroll
            for (int nt = 0; nt < 8; ++nt) {
                uint32_t b0 = __float_as_uint(kps[(nt * 8 + g) * QS_ + k]);
                uint32_t b1 = __float_as_uint(kps[(nt * 8 + g) * QS_ + k + 4]);
                mma_tf32(sacc[nt], a0, a1, a2, a3, b0, b1);
            }
        }

        // ---- online softmax on C-fragment layout ----
        const bool diag = (jt == it);
        float rm0 = -1e30f, rm1 = -1e30f;
        #pragma unroll
        for (int nt = 0; nt < 8; ++nt) {
            const int c0 = nt * 8 + 2 * t, c1 = c0 + 1;
            float v00 = sacc[nt][0] * SCL;
            float v01 = sacc[nt][1] * SCL;
            float v10 = sacc[nt][2] * SCL;
            float v11 = sacc[nt][3] * SCL;
            if (diag) {
                if (c0 > r0) v00 = -1e30f;
                if (c1 > r0) v01 = -1e30f;
                if (c0 > r1) v10 = -1e30f;
                if (c1 > r1) v11 = -1e30f;
            }
            sacc[nt][0] = v00; sacc[nt][1] = v01;
            sacc[nt][2] = v10; sacc[nt][3] = v11;
            rm0 = fmaxf(rm0, fmaxf(v00, v01));
            rm1 = fmaxf(rm1, fmaxf(v10, v11));
        }
        rm0 = fmaxf(rm0, __shfl_xor_sync(0xffffffffu, rm0, 1));
        rm0 = fmaxf(rm0, __shfl_xor_sync(0xffffffffu, rm0, 2));
        rm1 = fmaxf(rm1, __shfl_xor_sync(0xffffffffu, rm1, 1));
        rm1 = fmaxf(rm1, __shfl_xor_sync(0xffffffffu, rm1, 2));

        const float mn0 = fmaxf(m0, rm0), mn1 = fmaxf(m1, rm1);
        const float al0 = exp2f(m0 - mn0), al1 = exp2f(m1 - mn1);
        m0 = mn0; m1 = mn1;

        float rs0 = 0.f, rs1 = 0.f;
        #pragma unroll
        for (int nt = 0; nt < 8; ++nt) {
            float p00 = exp2f(sacc[nt][0] - mn0);
            float p01 = exp2f(sacc[nt][1] - mn0);
            float p10 = exp2f(sacc[nt][2] - mn1);
            float p11 = exp2f(sacc[nt][3] - mn1);
            sacc[nt][0] = p00; sacc[nt][1] = p01;
            sacc[nt][2] = p10; sacc[nt][3] = p11;
            rs0 += p00 + p01;
            rs1 += p10 + p11;
        }
        rs0 += __shfl_xor_sync(0xffffffffu, rs0, 1);
        rs0 += __shfl_xor_sync(0xffffffffu, rs0, 2);
        rs1 += __shfl_xor_sync(0xffffffffu, rs1, 1);
        rs1 += __shfl_xor_sync(0xffffffffu, rs1, 2);
        l0 = l0 * al0 + rs0;
        l1 = l1 * al1 + rs1;
        #pragma unroll
        for (int et = 0; et < 8; ++et) {
            oacc[et][0] *= al0; oacc[et][1] *= al0;
            oacc[et][2] *= al1; oacc[et][3] *= al1;
        }

        // ---- stage P (tf32) into smem, reuse K buffer ----
        __syncthreads();   // all K fragment reads done
        #pragma unroll
        for (int nt = 0; nt < 8; ++nt) {
            const int c0 = nt * 8 + 2 * t;
            float2 p0, p1;
            p0.x = __uint_as_float(f2tf32(sacc[nt][0]));
            p0.y = __uint_as_float(f2tf32(sacc[nt][1]));
            p1.x = __uint_as_float(f2tf32(sacc[nt][2]));
            p1.y = __uint_as_float(f2tf32(sacc[nt][3]));
            *reinterpret_cast<float2*>(kps + r0 * QS_ + c0) = p0;
            *reinterpret_cast<float2*>(kps + r1 * QS_ + c0) = p1;
        }
        __syncthreads();

        // ---- O += P V via tf32 mma ----
        #pragma unroll
        for (int j0 = 0; j0 < 8; ++j0) {
            const int j = j0 * 8 + t;
            uint32_t a0 = __float_as_uint(kps[r0 * QS_ + j]);
            uint32_t a1 = __float_as_uint(kps[r1 * QS_ + j]);
            uint32_t a2 = __float_as_uint(kps[r0 * QS_ + j + 4]);
            uint32_t a3 = __float_as_uint(kps[r1 * QS_ + j + 4]);
            #pragma unroll
            for (int et = 0; et < 8; ++et) {
                uint32_t b0 = __float_as_uint(vs[(j0 * 8 + t) * VS_ + et * 8 + g]);
                uint32_t b1 = __float_as_uint(vs[(j0 * 8 + t + 4) * VS_ + et * 8 + g]);
                mma_tf32(oacc[et], a0, a1, a2, a3, b0, b1);
            }
        }
    }

    // Epilogue: normalize, write O in [B,S,D] layout.
    const int b = bh >> 4, h = bh & 15;
    const float inv0 = 1.0f / l0, inv1 = 1.0f / l1;
    float* d0 = g_O + (size_t)(b * S_ + it * 64 + r0) * D_ + h * DK_;
    float* d1 = g_O + (size_t)(b * S_ + it * 64 + r1) * D_ + h * DK_;
    #pragma unroll
    for (int et = 0; et < 8; ++et) {
        const int c0 = et * 8 + 2 * t;
        float2 w0, w1;
        w0.x = oacc[et][0] * inv0; w0.y = oacc[et][1] * inv0;
        w1.x = oacc[et][2] * inv1; w1.y = oacc[et][3] * inv1;
        *reinterpret_cast<float2*>(d0 + c0) = w0;
        *reinterpret_cast<float2*>(d1 + c0) = w1;
    }
}

// ---------------------------------------------------------------------------
// Kernel 3: residual + LayerNorm. One CTA (256 thr) per (b,s) row, D=1024.
// ---------------------------------------------------------------------------
__global__ __launch_bounds__(256) void ln_res_kernel(
    const float* __restrict__ x,
    const float* __restrict__ gamma,
    const float* __restrict__ beta,
    float* __restrict__ out)
{
    const int row = blockIdx.x;
    const int tid = threadIdx.x;

    float4 ov = reinterpret_cast<const float4*>(g_O + (size_t)row * D_)[tid];
    float4 xv = reinterpret_cast<const float4*>(x   + (size_t)row * D_)[tid];
    float4 y;
    y.x = ov.x + xv.x; y.y = ov.y + xv.y; y.z = ov.z + xv.z; y.w = ov.w + xv.w;

    float s  = y.x + y.y + y.z + y.w;
    float ss = y.x * y.x + y.y * y.y + y.z * y.z + y.w * y.w;
    #pragma unroll
    for (int off = 16; off; off >>= 1) {
        s  += __shfl_xor_sync(0xffffffffu, s,  off);
        ss += __shfl_xor_sync(0xffffffffu, ss, off);
    }

    __shared__ float red[16];
    __shared__ float mu_s, rs_s;
    const int wid = tid >> 5;
    if ((tid & 31) == 0) { red[wid] = s; red[wid + 8] = ss; }
    __syncthreads();
    if (tid == 0) {
        float S = 0.f, SS = 0.f;
        #pragma unroll
        for (int i = 0; i < 8; ++i) { S += red[i]; SS += red[i + 8]; }
        float mu  = S * (1.0f / D_);
        float var = SS * (1.0f / D_) - mu * mu;
        mu_s = mu;
        rs_s = rsqrtf(var + 1e-5f);
    }
    __syncthreads();

    const float mu = mu_s, rstd = rs_s;
    float4 gv = reinterpret_cast<const float4*>(gamma)[tid];
    float4 bv = reinterpret_cast<const float4*>(beta)[tid];
    float4 r;
    r.x = (y.x - mu) * rstd * gv.x + bv.x;
    r.y = (y.y - mu) * rstd * gv.y + bv.y;
    r.z = (y.z - mu) * rstd * gv.z + bv.z;
    r.w = (y.w - mu) * rstd * gv.w + bv.w;
    reinterpret_cast<float4*>(out + (size_t)row * D_)[tid] = r;
}

// ---------------------------------------------------------------------------
extern "C" void kernel_launch(void* const* d_in, const int* in_sizes, int n_in,
                              void* d_out, int out_size)
{
    const float* x     = (const float*)d_in[0];
    const float* Wq    = (const float*)d_in[1];
    const float* bq    = (const float*)d_in[2];
    const float* Wk    = (const float*)d_in[3];
    const float* bk    = (const float*)d_in[4];
    const float* Wv    = (const float*)d_in[5];
    const float* bv    = (const float*)d_in[6];
    const float* gamma = (const float*)d_in[7];
    const float* beta  = (const float*)d_in[8];
    float* out = (float*)d_out;

    const int ATTN_SMEM = (2 * 64 * QS_ + 64 * VS_) * (int)sizeof(float); // 53248
    cudaFuncSetAttribute(attn_kernel,
                         cudaFuncAttributeMaxDynamicSharedMemorySize, ATTN_SMEM);

    qkv_proj_kernel<<<dim3((B_ * S_) / 64, H_), 256>>>(x, Wq, bq, Wk, bk, Wv, bv);
    attn_kernel<<<dim3(S_ / 64, BH_), 128, ATTN_SMEM>>>();
    ln_res_kernel<<<B_ * S_, 256>>>(x, gamma, beta, out);
}

// round 3
// speedup vs baseline: 2.6929x; 1.0282x over previous
#include <cuda_runtime.h>
#include <cstdint>
#include <cstddef>

#define B_  4
#define S_  2048
#define D_  1024
#define H_  16
#define DK_ 64
#define BH_ (B_ * H_)

// Scratch (allocation-free rule: __device__ globals). 32MB each.
__device__ float g_Q[B_ * H_ * S_ * DK_];
__device__ float g_K[B_ * H_ * S_ * DK_];
__device__ float g_V[B_ * H_ * S_ * DK_];
__device__ float g_O[B_ * S_ * D_];

__device__ __forceinline__ uint32_t f2tf32(float x) {
    uint32_t u;
    asm("cvt.rna.tf32.f32 %0, %1;" : "=r"(u) : "f"(x));
    return u;
}

__device__ __forceinline__ void mma_tf32(float* c,
                                         uint32_t a0, uint32_t a1,
                                         uint32_t a2, uint32_t a3,
                                         uint32_t b0, uint32_t b1) {
    asm volatile(
        "mma.sync.aligned.m16n8k8.row.col.f32.tf32.tf32.f32 "
        "{%0,%1,%2,%3}, {%4,%5,%6,%7}, {%8,%9}, {%0,%1,%2,%3};"
        : "+f"(c[0]), "+f"(c[1]), "+f"(c[2]), "+f"(c[3])
        : "r"(a0), "r"(a1), "r"(a2), "r"(a3), "r"(b0), "r"(b1));
}

__device__ __forceinline__ uint32_t sptr(const void* p) {
    return (uint32_t)__cvta_generic_to_shared(p);
}
#define CP16(dst_u32, src_ptr) \
    asm volatile("cp.async.cg.shared.global [%0], [%1], 16;" \
                 :: "r"(dst_u32), "l"(src_ptr))
#define CP_COMMIT() asm volatile("cp.async.commit_group;")
#define CP_WAIT0()  asm volatile("cp.async.wait_group 0;")

// ---------------------------------------------------------------------------
// Kernel 1: QKV projection via tf32 mma. Grid (BS/128, H), 256 threads.
// x slice in smem (stride 68, A-bank 4g+t), W[3] in smem (stride 72, B-bank
// 8t+g). A-fragments hoisted to regs once, reused across Q/K/V GEMMs.
// ---------------------------------------------------------------------------
#define XS_ 68
#define WS_ 72

__global__ __launch_bounds__(256) void qkv_proj_kernel(
    const float* __restrict__ x,
    const float* __restrict__ Wq, const float* __restrict__ bq,
    const float* __restrict__ Wk, const float* __restrict__ bk,
    const float* __restrict__ Wv, const float* __restrict__ bv)
{
    extern __shared__ float sm[];
    float* xs = sm;                    // 128*68
    float* ws = sm + 128 * XS_;        // 3 * 64*72

    const int h   = blockIdx.y;
    const int m0  = blockIdx.x * 128;
    const int tid = threadIdx.x;

    // Stage x tile (128 rows x 64 cols of head h).
    #pragma unroll
    for (int n = 0; n < 8; ++n) {
        int i = tid + 256 * n;
        int r = i >> 4, c = (i & 15) << 2;
        *reinterpret_cast<float4*>(xs + r * XS_ + c) =
            *reinterpret_cast<const float4*>(x + (size_t)(m0 + r) * D_ + h * DK_ + c);
    }
    // Stage the three 64x64 weight matrices (stride 72).
    const float* Wsrc[3] = {Wq, Wk, Wv};
    for (int p = 0; p < 3; ++p) {
        const float* wsrc = Wsrc[p] + h * DK_ * DK_;
        for (int i = tid; i < 1024; i += 256) {
            int r = i >> 4, c = (i & 15) << 2;
            *reinterpret_cast<float4*>(ws + p * 64 * WS_ + r * WS_ + c) =
                *reinterpret_cast<const float4*>(wsrc + r * 64 + c);
        }
    }
    __syncthreads();

    const int lane = tid & 31, warp = tid >> 5;
    const int g = lane >> 2, t = lane & 3;
    const int r0 = warp * 16 + g, r1 = r0 + 8;

    uint32_t af[8][4];
    #pragma unroll
    for (int k0 = 0; k0 < 8; ++k0) {
        af[k0][0] = __float_as_uint(xs[r0 * XS_ + 8 * k0 + t]);
        af[k0][1] = __float_as_uint(xs[r1 * XS_ + 8 * k0 + t]);
        af[k0][2] = __float_as_uint(xs[r0 * XS_ + 8 * k0 + t + 4]);
        af[k0][3] = __float_as_uint(xs[r1 * XS_ + 8 * k0 + t + 4]);
    }

    const float* Bs[3] = {bq, bk, bv};
    float*       Ds[3] = {g_Q, g_K, g_V};
    const int b  = m0 >> 11;
    const int s0 = m0 & (S_ - 1);

    for (int p = 0; p < 3; ++p) {
        const float* w = ws + p * 64 * WS_;
        float acc[8][4];
        #pragma unroll
        for (int nt = 0; nt < 8; ++nt)
            #pragma unroll
            for (int q = 0; q < 4; ++q) acc[nt][q] = 0.f;

        #pragma unroll
        for (int k0 = 0; k0 < 8; ++k0)
            #pragma unroll
            for (int nt = 0; nt < 8; ++nt) {
                uint32_t b0 = __float_as_uint(w[(8 * k0 + t)     * WS_ + nt * 8 + g]);
                uint32_t b1 = __float_as_uint(w[(8 * k0 + t + 4) * WS_ + nt * 8 + g]);
                mma_tf32(acc[nt], af[k0][0], af[k0][1], af[k0][2], af[k0][3], b0, b1);
            }

        float* dst = Ds[p] + ((size_t)(b * H_ + h) * S_ + s0) * DK_;
        const float* bias = Bs[p] + h * DK_;
        #pragma unroll
        for (int nt = 0; nt < 8; ++nt) {
            const int c0 = nt * 8 + 2 * t;
            float bx = bias[c0], by = bias[c0 + 1];
            *reinterpret_cast<float2*>(dst + (size_t)r0 * DK_ + c0) =
                make_float2(acc[nt][0] + bx, acc[nt][1] + by);
            *reinterpret_cast<float2*>(dst + (size_t)r1 * DK_ + c0) =
                make_float2(acc[nt][2] + bx, acc[nt][3] + by);
        }
    }
}

// ---------------------------------------------------------------------------
// Kernel 2: causal flash attention, tf32 mma, BM=128, BN=64, 256 threads.
// Q fragments in registers; K/V double-buffered via cp.async; P has its own
// smem buffer (stride 68). One __syncthreads per kv-tile.
// ---------------------------------------------------------------------------
#define PS_ 68
#define VS_ 72
// smem float offsets
#define OFF_P  0
#define OFF_K0 (128 * PS_)            // 8704
#define OFF_K1 (OFF_K0 + 64 * PS_)    // 13056
#define OFF_V0 (OFF_K1 + 64 * PS_)    // 17408
#define OFF_V1 (OFF_V0 + 64 * VS_)    // 22016
#define ATTN_SMEM_FLOATS (OFF_V1 + 64 * VS_)   // 26624 -> 106496 B

__device__ __forceinline__ void kv_issue(float* kb, float* vb,
                                         const float* Kp, const float* Vp,
                                         int tid)
{
    #pragma unroll
    for (int n = 0; n < 4; ++n) {
        int i = tid + 256 * n;
        int r = i >> 4, c = (i & 15) << 2;
        CP16(sptr(kb + r * PS_ + c), Kp + r * 64 + c);
        CP16(sptr(vb + r * VS_ + c), Vp + r * 64 + c);
    }
}

__global__ __launch_bounds__(256) void attn_kernel()
{
    extern __shared__ float smx[];
    float* ps = smx + OFF_P;
    float* kb[2] = { smx + OFF_K0, smx + OFF_K1 };
    float* vb[2] = { smx + OFF_V0, smx + OFF_V1 };

    const int it   = (gridDim.x - 1) - blockIdx.x;   // heavy tiles first
    const int bh   = blockIdx.y;
    const int tid  = threadIdx.x;
    const int lane = tid & 31, warp = tid >> 5;
    const int g    = lane >> 2, t = lane & 3;
    const int r0   = warp * 16 + g, r1 = r0 + 8;

    const float* Kbase = g_K + (size_t)bh * S_ * DK_;
    const float* Vbase = g_V + (size_t)bh * S_ * DK_;

    // Prefetch kv-tile 0.
    kv_issue(kb[0], vb[0], Kbase, Vbase, tid);
    CP_COMMIT();

    // Stage Q through the P buffer, then lift fragments to registers.
    const float* Qp = g_Q + ((size_t)bh * S_ + it * 128) * DK_;
    #pragma unroll
    for (int n = 0; n < 8; ++n) {
        int i = tid + 256 * n;
        int r = i >> 4, c = (i & 15) << 2;
        *reinterpret_cast<float4*>(ps + r * PS_ + c) =
            *reinterpret_cast<const float4*>(Qp + r * 64 + c);
    }
    __syncthreads();
    uint32_t qf[8][4];
    #pragma unroll
    for (int k0 = 0; k0 < 8; ++k0) {
        qf[k0][0] = __float_as_uint(ps[r0 * PS_ + 8 * k0 + t]);
        qf[k0][1] = __float_as_uint(ps[r1 * PS_ + 8 * k0 + t]);
        qf[k0][2] = __float_as_uint(ps[r0 * PS_ + 8 * k0 + t + 4]);
        qf[k0][3] = __float_as_uint(ps[r1 * PS_ + 8 * k0 + t + 4]);
    }

    float m0 = -1e30f, m1 = -1e30f, l0 = 0.f, l1 = 0.f;
    float oacc[8][4];
    #pragma unroll
    for (int et = 0; et < 8; ++et)
        #pragma unroll
        for (int q = 0; q < 4; ++q) oacc[et][q] = 0.f;

    const float SCL = 0.18033688011112042f;  // log2(e)/sqrt(DK)
    const int jtmax = 2 * it + 1;

    for (int jt = 0; jt <= jtmax; ++jt) {
        CP_WAIT0();          // kv-tile jt landed (only pending group)
        __syncthreads();     // visible to all; all warps done with iter jt-1

        if (jt < jtmax) {    // prefetch jt+1 into the other buffer
            kv_issue(kb[(jt + 1) & 1], vb[(jt + 1) & 1],
                     Kbase + (size_t)(jt + 1) * 64 * DK_,
                     Vbase + (size_t)(jt + 1) * 64 * DK_, tid);
            CP_COMMIT();
        }
        const float* ks = kb[jt & 1];
        const float* vs = vb[jt & 1];

        // ---- S = Q K^T ----
        float sacc[8][4];
        #pragma unroll
        for (int nt = 0; nt < 8; ++nt)
            #pragma unroll
            for (int q = 0; q < 4; ++q) sacc[nt][q] = 0.f;

        #pragma unroll
        for (int k0 = 0; k0 < 8; ++k0)
            #pragma unroll
            for (int nt = 0; nt < 8; ++nt) {
                uint32_t b0 = __float_as_uint(ks[(nt * 8 + g) * PS_ + 8 * k0 + t]);
                uint32_t b1 = __float_as_uint(ks[(nt * 8 + g) * PS_ + 8 * k0 + t + 4]);
                mma_tf32(sacc[nt], qf[k0][0], qf[k0][1], qf[k0][2], qf[k0][3], b0, b1);
            }

        // ---- online softmax ----
        const bool diag = (jt >= 2 * it);
        const int  coff = (jt - 2 * it) * 64;
        float rm0 = -1e30f, rm1 = -1e30f;
        #pragma unroll
        for (int nt = 0; nt < 8; ++nt) {
            const int c0 = nt * 8 + 2 * t;
            float v00 = sacc[nt][0] * SCL;
            float v01 = sacc[nt][1] * SCL;
            float v10 = sacc[nt][2] * SCL;
            float v11 = sacc[nt][3] * SCL;
            if (diag) {
                if (c0 + coff     > r0) v00 = -1e30f;
                if (c0 + 1 + coff > r0) v01 = -1e30f;
                if (c0 + coff     > r1) v10 = -1e30f;
                if (c0 + 1 + coff > r1) v11 = -1e30f;
            }
            sacc[nt][0] = v00; sacc[nt][1] = v01;
            sacc[nt][2] = v10; sacc[nt][3] = v11;
            rm0 = fmaxf(rm0, fmaxf(v00, v01));
            rm1 = fmaxf(rm1, fmaxf(v10, v11));
        }
        rm0 = fmaxf(rm0, __shfl_xor_sync(0xffffffffu, rm0, 1));
        rm0 = fmaxf(rm0, __shfl_xor_sync(0xffffffffu, rm0, 2));
        rm1 = fmaxf(rm1, __shfl_xor_sync(0xffffffffu, rm1, 1));
        rm1 = fmaxf(rm1, __shfl_xor_sync(0xffffffffu, rm1, 2));

        const float mn0 = fmaxf(m0, rm0), mn1 = fmaxf(m1, rm1);
        const float al0 = exp2f(m0 - mn0), al1 = exp2f(m1 - mn1);
        m0 = mn0; m1 = mn1;

        float rs0 = 0.f, rs1 = 0.f;
        #pragma unroll
        for (int nt = 0; nt < 8; ++nt) {
            float p00 = exp2f(sacc[nt][0] - mn0);
            float p01 = exp2f(sacc[nt][1] - mn0);
            float p10 = exp2f(sacc[nt][2] - mn1);
            float p11 = exp2f(sacc[nt][3] - mn1);
            sacc[nt][0] = p00; sacc[nt][1] = p01;
            sacc[nt][2] = p10; sacc[nt][3] = p11;
            rs0 += p00 + p01;
            rs1 += p10 + p11;
        }
        rs0 += __shfl_xor_sync(0xffffffffu, rs0, 1);
        rs0 += __shfl_xor_sync(0xffffffffu, rs0, 2);
        rs1 += __shfl_xor_sync(0xffffffffu, rs1, 1);
        rs1 += __shfl_xor_sync(0xffffffffu, rs1, 2);
        l0 = l0 * al0 + rs0;
        l1 = l1 * al1 + rs1;
        #pragma unroll
        for (int et = 0; et < 8; ++et) {
            oacc[et][0] *= al0; oacc[et][1] *= al0;
            oacc[et][2] *= al1; oacc[et][3] *= al1;
        }

        // ---- stage P (rounded tf32); warp owns its 16 rows -> warp sync only
        __syncwarp();
        #pragma unroll
        for (int nt = 0; nt < 8; ++nt) {
            const int c0 = nt * 8 + 2 * t;
            float2 p0, p1;
            p0.x = __uint_as_float(f2tf32(sacc[nt][0]));
            p0.y = __uint_as_float(f2tf32(sacc[nt][1]));
            p1.x = __uint_as_float(f2tf32(sacc[nt][2]));
            p1.y = __uint_as_float(f2tf32(sacc[nt][3]));
            *reinterpret_cast<float2*>(ps + r0 * PS_ + c0) = p0;
            *reinterpret_cast<float2*>(ps + r1 * PS_ + c0) = p1;
        }
        __syncwarp();

        // ---- O += P V ----
        #pragma unroll
        for (int j0 = 0; j0 < 8; ++j0) {
            uint32_t a0 = __float_as_uint(ps[r0 * PS_ + 8 * j0 + t]);
            uint32_t a1 = __float_as_uint(ps[r1 * PS_ + 8 * j0 + t]);
            uint32_t a2 = __float_as_uint(ps[r0 * PS_ + 8 * j0 + t + 4]);
            uint32_t a3 = __float_as_uint(ps[r1 * PS_ + 8 * j0 + t + 4]);
            #pragma unroll
            for (int et = 0; et < 8; ++et) {
                uint32_t b0 = __float_as_uint(vs[(j0 * 8 + t)     * VS_ + et * 8 + g]);
                uint32_t b1 = __float_as_uint(vs[(j0 * 8 + t + 4) * VS_ + et * 8 + g]);
                mma_tf32(oacc[et], a0, a1, a2, a3, b0, b1);
            }
        }
    }

    // Epilogue: normalize, write O in [B,S,D] layout.
    const int b = bh >> 4, h = bh & 15;
    const float inv0 = 1.0f / l0, inv1 = 1.0f / l1;
    float* d0 = g_O + (size_t)(b * S_ + it * 128 + r0) * D_ + h * DK_;
    float* d1 = g_O + (size_t)(b * S_ + it * 128 + r1) * D_ + h * DK_;
    #pragma unroll
    for (int et = 0; et < 8; ++et) {
        const int c0 = et * 8 + 2 * t;
        *reinterpret_cast<float2*>(d0 + c0) =
            make_float2(oacc[et][0] * inv0, oacc[et][1] * inv0);
        *reinterpret_cast<float2*>(d1 + c0) =
            make_float2(oacc[et][2] * inv1, oacc[et][3] * inv1);
    }
}

// ---------------------------------------------------------------------------
// Kernel 3: residual + LayerNorm. One CTA (256 thr) per (b,s) row, D=1024.
// ---------------------------------------------------------------------------
__global__ __launch_bounds__(256) void ln_res_kernel(
    const float* __restrict__ x,
    const float* __restrict__ gamma,
    const float* __restrict__ beta,
    float* __restrict__ out)
{
    const int row = blockIdx.x;
    const int tid = threadIdx.x;

    float4 ov = reinterpret_cast<const float4*>(g_O + (size_t)row * D_)[tid];
    float4 xv = reinterpret_cast<const float4*>(x   + (size_t)row * D_)[tid];
    float4 y;
    y.x = ov.x + xv.x; y.y = ov.y + xv.y; y.z = ov.z + xv.z; y.w = ov.w + xv.w;

    float s  = y.x + y.y + y.z + y.w;
    float ss = y.x * y.x + y.y * y.y + y.z * y.z + y.w * y.w;
    #pragma unroll
    for (int off = 16; off; off >>= 1) {
        s  += __shfl_xor_sync(0xffffffffu, s,  off);
        ss += __shfl_xor_sync(0xffffffffu, ss, off);
    }

    __shared__ float red[16];
    __shared__ float mu_s, rs_s;
    const int wid = tid >> 5;
    if ((tid & 31) == 0) { red[wid] = s; red[wid + 8] = ss; }
    __syncthreads();
    if (tid == 0) {
        float S = 0.f, SS = 0.f;
        #pragma unroll
        for (int i = 0; i < 8; ++i) { S += red[i]; SS += red[i + 8]; }
        float mu  = S * (1.0f / D_);
        float var = SS * (1.0f / D_) - mu * mu;
        mu_s = mu;
        rs_s = rsqrtf(var + 1e-5f);
    }
    __syncthreads();

    const float mu = mu_s, rstd = rs_s;
    float4 gv = reinterpret_cast<const float4*>(gamma)[tid];
    float4 bv = reinterpret_cast<const float4*>(beta)[tid];
    float4 r;
    r.x = (y.x - mu) * rstd * gv.x + bv.x;
    r.y = (y.y - mu) * rstd * gv.y + bv.y;
    r.z = (y.z - mu) * rstd * gv.z + bv.z;
    r.w = (y.w - mu) * rstd * gv.w + bv.w;
    reinterpret_cast<float4*>(out + (size_t)row * D_)[tid] = r;
}

// ---------------------------------------------------------------------------
extern "C" void kernel_launch(void* const* d_in, const int* in_sizes, int n_in,
                              void* d_out, int out_size)
{
    const float* x     = (const float*)d_in[0];
    const float* Wq    = (const float*)d_in[1];
    const float* bq    = (const float*)d_in[2];
    const float* Wk    = (const float*)d_in[3];
    const float* bk    = (const float*)d_in[4];
    const float* Wv    = (const float*)d_in[5];
    const float* bv    = (const float*)d_in[6];
    const float* gamma = (const float*)d_in[7];
    const float* beta  = (const float*)d_in[8];
    float* out = (float*)d_out;

    const int QKV_SMEM  = (128 * XS_ + 3 * 64 * WS_) * (int)sizeof(float);  // 90112
    const int ATTN_SMEM = ATTN_SMEM_FLOATS * (int)sizeof(float);            // 106496
    cudaFuncSetAttribute(qkv_proj_kernel,
                         cudaFuncAttributeMaxDynamicSharedMemorySize, QKV_SMEM);
    cudaFuncSetAttribute(attn_kernel,
                         cudaFuncAttributeMaxDynamicSharedMemorySize, ATTN_SMEM);

    qkv_proj_kernel<<<dim3((B_ * S_) / 128, H_), 256, QKV_SMEM>>>(
        x, Wq, bq, Wk, bk, Wv, bv);
    attn_kernel<<<dim3(S_ / 128, BH_), 256, ATTN_SMEM>>>();
    ln_res_kernel<<<B_ * S_, 256>>>(x, gamma, beta, out);
}

// round 5
// speedup vs baseline: 3.5010x; 1.3001x over previous
#include <cuda_runtime.h>
#include <cuda_bf16.h>
#include <cstdint>
#include <cstddef>

#define B_  4
#define S_  2048
#define D_  1024
#define H_  16
#define DK_ 64
#define BH_ (B_ * H_)

// Scratch (allocation-free rule: __device__ globals).
__device__ float g_Q[BH_ * S_ * DK_];           // [bh][s][dk] fp32
__device__ float g_K[BH_ * S_ * DK_];           // [bh][s][dk] fp32, cols PERMUTED
__device__ __nv_bfloat16 g_Vt[BH_ * DK_ * S_];  // [bh][feat][key] bf16
__device__ float g_O[B_ * S_ * D_];

// ---------------------------------------------------------------------------
// helpers
// ---------------------------------------------------------------------------
__device__ __forceinline__ void mma_tf32(float* c,
                                         uint32_t a0, uint32_t a1,
                                         uint32_t a2, uint32_t a3,
                                         uint32_t b0, uint32_t b1) {
    asm volatile(
        "mma.sync.aligned.m16n8k8.row.col.f32.tf32.tf32.f32 "
        "{%0,%1,%2,%3}, {%4,%5,%6,%7}, {%8,%9}, {%0,%1,%2,%3};"
        : "+f"(c[0]), "+f"(c[1]), "+f"(c[2]), "+f"(c[3])
        : "r"(a0), "r"(a1), "r"(a2), "r"(a3), "r"(b0), "r"(b1));
}
__device__ __forceinline__ void mma_bf16(float* c,
                                         uint32_t a0, uint32_t a1,
                                         uint32_t a2, uint32_t a3,
                                         uint32_t b0, uint32_t b1) {
    asm volatile(
        "mma.sync.aligned.m16n8k16.row.col.f32.bf16.bf16.f32 "
        "{%0,%1,%2,%3}, {%4,%5,%6,%7}, {%8,%9}, {%0,%1,%2,%3};"
        : "+f"(c[0]), "+f"(c[1]), "+f"(c[2]), "+f"(c[3])
        : "r"(a0), "r"(a1), "r"(a2), "r"(a3), "r"(b0), "r"(b1));
}
__device__ __forceinline__ uint32_t packbf(float lo, float hi) {
    uint32_t r;
    asm("cvt.rn.bf16x2.f32 %0, %1, %2;" : "=r"(r) : "f"(hi), "f"(lo));
    return r;
}
__device__ __forceinline__ float ex2(float x) {
    float y; asm("ex2.approx.ftz.f32 %0, %1;" : "=f"(y) : "f"(x)); return y;
}
__device__ __forceinline__ uint32_t sptr(const void* p) {
    return (uint32_t)__cvta_generic_to_shared(p);
}
#define CP16(dst_u32, src_ptr) \
    asm volatile("cp.async.cg.shared.global [%0], [%1], 16;" \
                 :: "r"(dst_u32), "l"(src_ptr))
#define CP_COMMIT() asm volatile("cp.async.commit_group;")
#define CP_WAIT0()  asm volatile("cp.async.wait_group 0;" ::: "memory")

// K column permutation: within each 8-block, j -> (j&3)*2 + (j>>2), so the
// tf32 B-fragment pair (k=t, k=t+4) sits at adjacent floats -> one LDS.64.
__device__ __forceinline__ int kperm(int c) {
    return (c & ~7) | (((c & 3) << 1) | ((c >> 2) & 1));
}

// ---------------------------------------------------------------------------
// Kernel 1: QKV projection via tf32 mma. Grid (BS/128, H), 256 threads.
// Epilogue: Q fp32, K fp32 (cols permuted), V bf16 transposed [feat][key].
// ---------------------------------------------------------------------------
#define XS_ 68
#define WS_ 72

__global__ __launch_bounds__(256) void qkv_proj_kernel(
    const float* __restrict__ x,
    const float* __restrict__ Wq, const float* __restrict__ bq,
    const float* __restrict__ Wk, const float* __restrict__ bk,
    const float* __restrict__ Wv, const float* __restrict__ bv)
{
    extern __shared__ float sm[];
    float* xs = sm;
    float* ws = sm + 128 * XS_;

    const int h   = blockIdx.y;
    const int m0  = blockIdx.x * 128;
    const int tid = threadIdx.x;

    #pragma unroll
    for (int n = 0; n < 8; ++n) {
        int i = tid + 256 * n;
        int r = i >> 4, c = (i & 15) << 2;
        *reinterpret_cast<float4*>(xs + r * XS_ + c) =
            *reinterpret_cast<const float4*>(x + (size_t)(m0 + r) * D_ + h * DK_ + c);
    }
    const float* Wsrc[3] = {Wq, Wk, Wv};
    for (int p = 0; p < 3; ++p) {
        const float* wsrc = Wsrc[p] + h * DK_ * DK_;
        for (int i = tid; i < 1024; i += 256) {
            int r = i >> 4, c = (i & 15) << 2;
            *reinterpret_cast<float4*>(ws + p * 64 * WS_ + r * WS_ + c) =
                *reinterpret_cast<const float4*>(wsrc + r * 64 + c);
        }
    }
    __syncthreads();

    const int lane = tid & 31, warp = tid >> 5;
    const int g = lane >> 2, t = lane & 3;
    const int r0 = warp * 16 + g, r1 = r0 + 8;

    uint32_t af[8][4];
    #pragma unroll
    for (int k0 = 0; k0 < 8; ++k0) {
        af[k0][0] = __float_as_uint(xs[r0 * XS_ + 8 * k0 + t]);
        af[k0][1] = __float_as_uint(xs[r1 * XS_ + 8 * k0 + t]);
        af[k0][2] = __float_as_uint(xs[r0 * XS_ + 8 * k0 + t + 4]);
        af[k0][3] = __float_as_uint(xs[r1 * XS_ + 8 * k0 + t + 4]);
    }

    const float* Bs[3] = {bq, bk, bv};
    const int b  = m0 >> 11;
    const int s0 = m0 & (S_ - 1);
    const int bh = b * H_ + h;

    for (int p = 0; p < 3; ++p) {
        const float* w = ws + p * 64 * WS_;
        float acc[8][4];
        #pragma unroll
        for (int nt = 0; nt < 8; ++nt)
            #pragma unroll
            for (int q = 0; q < 4; ++q) acc[nt][q] = 0.f;

        #pragma unroll
        for (int k0 = 0; k0 < 8; ++k0)
            #pragma unroll
            for (int nt = 0; nt < 8; ++nt) {
                uint32_t b0 = __float_as_uint(w[(8 * k0 + t)     * WS_ + nt * 8 + g]);
                uint32_t b1 = __float_as_uint(w[(8 * k0 + t + 4) * WS_ + nt * 8 + g]);
                mma_tf32(acc[nt], af[k0][0], af[k0][1], af[k0][2], af[k0][3], b0, b1);
            }

        const float* bias = Bs[p] + h * DK_;
        if (p == 0) {
            float* dst = g_Q + ((size_t)bh * S_ + s0) * DK_;
            #pragma unroll
            for (int nt = 0; nt < 8; ++nt) {
                const int c0 = nt * 8 + 2 * t;
                float bx = bias[c0], by = bias[c0 + 1];
                *reinterpret_cast<float2*>(dst + (size_t)r0 * DK_ + c0) =
                    make_float2(acc[nt][0] + bx, acc[nt][1] + by);
                *reinterpret_cast<float2*>(dst + (size_t)r1 * DK_ + c0) =
                    make_float2(acc[nt][2] + bx, acc[nt][3] + by);
            }
        } else if (p == 1) {
            float* dst = g_K + ((size_t)bh * S_ + s0) * DK_;
            #pragma unroll
            for (int nt = 0; nt < 8; ++nt) {
                const int c0 = nt * 8 + 2 * t;
                float bx = bias[c0], by = bias[c0 + 1];
                const int p0 = kperm(c0), p1 = kperm(c0 + 1);
                dst[(size_t)r0 * DK_ + p0] = acc[nt][0] + bx;
                dst[(size_t)r0 * DK_ + p1] = acc[nt][1] + by;
                dst[(size_t)r1 * DK_ + p0] = acc[nt][2] + bx;
                dst[(size_t)r1 * DK_ + p1] = acc[nt][3] + by;
            }
        } else {
            #pragma unroll
            for (int nt = 0; nt < 8; ++nt) {
                const int c0 = nt * 8 + 2 * t;
                float bx = bias[c0], by = bias[c0 + 1];
                g_Vt[((size_t)bh * DK_ + c0)     * S_ + s0 + r0] =
                    __float2bfloat16(acc[nt][0] + bx);
                g_Vt[((size_t)bh * DK_ + c0 + 1) * S_ + s0 + r0] =
                    __float2bfloat16(acc[nt][1] + by);
                g_Vt[((size_t)bh * DK_ + c0)     * S_ + s0 + r1] =
                    __float2bfloat16(acc[nt][2] + bx);
                g_Vt[((size_t)bh * DK_ + c0 + 1) * S_ + s0 + r1] =
                    __float2bfloat16(acc[nt][3] + by);
            }
        }
    }
}

// ---------------------------------------------------------------------------
// Kernel 2: flash attention, BM=128, BN=64, 256 threads (8 warps).
// QK: tf32 m16n8k8 (Q frags in regs, K LDS.64 from permuted smem).
// PV: bf16 m16n8k16 (P packed in regs from softmax; V via ldmatrix.x4).
// K/V double-buffered cp.async; ONE __syncthreads per kv-tile.
// ---------------------------------------------------------------------------
#define KS_ 68
#define OFFK0 0
#define OFFK1 17408
#define OFFV0 34816
#define OFFV1 43008
#define ATTN_SMEM 51200

__device__ __forceinline__ void stage_k(uint32_t dst, const float* src, int tid) {
    #pragma unroll
    for (int n = 0; n < 4; ++n) {
        int i = tid + 256 * n;
        int r = i >> 4, c = i & 15;
        CP16(dst + r * (KS_ * 4) + c * 16, src + r * DK_ + c * 4);
    }
}
__device__ __forceinline__ void stage_v(uint32_t dst, const __nv_bfloat16* Vb,
                                        int jt, int tid) {
    #pragma unroll
    for (int n = 0; n < 2; ++n) {
        int i = tid + 256 * n;
        int r = i >> 3, c = i & 7;
        CP16(dst + r * 128 + ((c * 16) ^ ((r & 7) * 16)),
             Vb + (size_t)r * S_ + jt * 64 + c * 8);
    }
}

__global__ __launch_bounds__(256, 2) void attn_kernel()
{
    extern __shared__ char smem[];
    const uint32_t sb = sptr(smem);

    const int it   = (gridDim.x - 1) - blockIdx.x;   // heavy tiles first
    const int bh   = blockIdx.y;
    const int tid  = threadIdx.x;
    const int lane = tid & 31, warp = tid >> 5;
    const int g    = lane >> 2, t = lane & 3;
    const int r0   = warp * 16 + g, r1 = r0 + 8;

    const float* Kb = g_K + (size_t)bh * S_ * DK_;
    const __nv_bfloat16* Vb = g_Vt + (size_t)bh * DK_ * S_;

    // Stage kv-tile 0.
    stage_k(sb + OFFK0, Kb, tid);
    stage_v(sb + OFFV0, Vb, 0, tid);
    CP_COMMIT();

    // Q fragments straight from gmem (once per CTA).
    const float* Qp = g_Q + ((size_t)bh * S_ + it * 128) * DK_;
    uint32_t qf[8][4];
    #pragma unroll
    for (int k0 = 0; k0 < 8; ++k0) {
        qf[k0][0] = __float_as_uint(Qp[(size_t)r0 * DK_ + 8 * k0 + t]);
        qf[k0][1] = __float_as_uint(Qp[(size_t)r1 * DK_ + 8 * k0 + t]);
        qf[k0][2] = __float_as_uint(Qp[(size_t)r0 * DK_ + 8 * k0 + t + 4]);
        qf[k0][3] = __float_as_uint(Qp[(size_t)r1 * DK_ + 8 * k0 + t + 4]);
    }

    float m0 = -1e30f, m1 = -1e30f, l0 = 0.f, l1 = 0.f;
    float oacc[8][4];
    #pragma unroll
    for (int et = 0; et < 8; ++et)
        #pragma unroll
        for (int q = 0; q < 4; ++q) oacc[et][q] = 0.f;

    const float SCL = 0.18033688011112042f;  // log2(e)/sqrt(DK)
    const int jtmax = 2 * it + 1;

    for (int jt = 0; jt <= jtmax; ++jt) {
        CP_WAIT0();
        __syncthreads();       // tile jt staged & all warps done with jt-1

        const int cur = jt & 1;
        if (jt < jtmax) {      // prefetch jt+1 into the other buffer
            stage_k(sb + (cur ? OFFK0 : OFFK1), Kb + (size_t)(jt + 1) * 64 * DK_, tid);
            stage_v(sb + (cur ? OFFV0 : OFFV1), Vb, jt + 1, tid);
            CP_COMMIT();
        }

        // ---- S = Q K^T (tf32; LDS.64 pairs thanks to permuted K) ----
        const float* ks = (const float*)(smem + (cur ? OFFK1 : OFFK0));
        float sacc[8][4];
        #pragma unroll
        for (int nt = 0; nt < 8; ++nt)
            #pragma unroll
            for (int q = 0; q < 4; ++q) sacc[nt][q] = 0.f;

        #pragma unroll
        for (int k0 = 0; k0 < 8; ++k0)
            #pragma unroll
            for (int nt = 0; nt < 8; ++nt) {
                float2 kk = *reinterpret_cast<const float2*>(
                    ks + (nt * 8 + g) * KS_ + 8 * k0 + 2 * t);
                mma_tf32(sacc[nt], qf[k0][0], qf[k0][1], qf[k0][2], qf[k0][3],
                         __float_as_uint(kk.x), __float_as_uint(kk.y));
            }

        // ---- online softmax (C-fragment layout) ----
        const bool diag = (jt >= 2 * it);
        const int  coff = (jt - 2 * it) * 64;
        float rm0 = -1e30f, rm1 = -1e30f;
        #pragma unroll
        for (int nt = 0; nt < 8; ++nt) {
            const int c0 = nt * 8 + 2 * t;
            float v00 = sacc[nt][0] * SCL;
            float v01 = sacc[nt][1] * SCL;
            float v10 = sacc[nt][2] * SCL;
            float v11 = sacc[nt][3] * SCL;
            if (diag) {
                if (c0 + coff     > r0) v00 = -1e30f;
                if (c0 + 1 + coff > r0) v01 = -1e30f;
                if (c0 + coff     > r1) v10 = -1e30f;
                if (c0 + 1 + coff > r1) v11 = -1e30f;
            }
            sacc[nt][0] = v00; sacc[nt][1] = v01;
            sacc[nt][2] = v10; sacc[nt][3] = v11;
            rm0 = fmaxf(rm0, fmaxf(v00, v01));
            rm1 = fmaxf(rm1, fmaxf(v10, v11));
        }
        rm0 = fmaxf(rm0, __shfl_xor_sync(0xffffffffu, rm0, 1));
        rm0 = fmaxf(rm0, __shfl_xor_sync(0xffffffffu, rm0, 2));
        rm1 = fmaxf(rm1, __shfl_xor_sync(0xffffffffu, rm1, 1));
        rm1 = fmaxf(rm1, __shfl_xor_sync(0xffffffffu, rm1, 2));

        const float mn0 = fmaxf(m0, rm0), mn1 = fmaxf(m1, rm1);
        const float al0 = ex2(m0 - mn0), al1 = ex2(m1 - mn1);
        m0 = mn0; m1 = mn1;

        float rs0 = 0.f, rs1 = 0.f;
        #pragma unroll
        for (int nt = 0; nt < 8; ++nt) {
            float p00 = ex2(sacc[nt][0] - mn0);
            float p01 = ex2(sacc[nt][1] - mn0);
            float p10 = ex2(sacc[nt][2] - mn1);
            float p11 = ex2(sacc[nt][3] - mn1);
            sacc[nt][0] = p00; sacc[nt][1] = p01;
            sacc[nt][2] = p10; sacc[nt][3] = p11;
            rs0 += p00 + p01;
            rs1 += p10 + p11;
        }
        rs0 += __shfl_xor_sync(0xffffffffu, rs0, 1);
        rs0 += __shfl_xor_sync(0xffffffffu, rs0, 2);
        rs1 += __shfl_xor_sync(0xffffffffu, rs1, 1);
        rs1 += __shfl_xor_sync(0xffffffffu, rs1, 2);
        l0 = l0 * al0 + rs0;
        l1 = l1 * al1 + rs1;
        #pragma unroll
        for (int et = 0; et < 8; ++et) {
            oacc[et][0] *= al0; oacc[et][1] *= al0;
            oacc[et][2] *= al1; oacc[et][3] *= al1;
        }

        // ---- pack P into bf16 A-fragments (pure registers) ----
        uint32_t pa[4][4];
        #pragma unroll
        for (int kt = 0; kt < 4; ++kt) {
            pa[kt][0] = packbf(sacc[2 * kt][0],     sacc[2 * kt][1]);
            pa[kt][1] = packbf(sacc[2 * kt][2],     sacc[2 * kt][3]);
            pa[kt][2] = packbf(sacc[2 * kt + 1][0], sacc[2 * kt + 1][1]);
            pa[kt][3] = packbf(sacc[2 * kt + 1][2], sacc[2 * kt + 1][3]);
        }

        // ---- O += P V (bf16 m16n8k16; V via ldmatrix.x4) ----
        const uint32_t vb32 = sb + (cur ? OFFV1 : OFFV0);
        #pragma unroll
        for (int p2 = 0; p2 < 2; ++p2) {
            #pragma unroll
            for (int nt = 0; nt < 8; ++nt) {
                const int row = nt * 8 + (lane & 7);
                const int cg  = p2 * 4 + (lane >> 3);
                uint32_t addr = vb32 + row * 128 + ((cg * 16) ^ ((row & 7) * 16));
                uint32_t bb0, bb1, bb2, bb3;
                asm volatile(
                    "ldmatrix.sync.aligned.m8n8.x4.shared.b16 {%0,%1,%2,%3}, [%4];"
                    : "=r"(bb0), "=r"(bb1), "=r"(bb2), "=r"(bb3) : "r"(addr));
                mma_bf16(oacc[nt], pa[2*p2][0], pa[2*p2][1], pa[2*p2][2], pa[2*p2][3],
                         bb0, bb1);
                mma_bf16(oacc[nt], pa[2*p2+1][0], pa[2*p2+1][1], pa[2*p2+1][2],
                         pa[2*p2+1][3], bb2, bb3);
            }
        }
    }

    // Epilogue: normalize, write O in [B,S,D] layout.
    const int b = bh >> 4, h = bh & 15;
    const float inv0 = 1.0f / l0, inv1 = 1.0f / l1;
    float* d0 = g_O + (size_t)(b * S_ + it * 128 + r0) * D_ + h * DK_;
    float* d1 = g_O + (size_t)(b * S_ + it * 128 + r1) * D_ + h * DK_;
    #pragma unroll
    for (int et = 0; et < 8; ++et) {
        const int c0 = et * 8 + 2 * t;
        *reinterpret_cast<float2*>(d0 + c0) =
            make_float2(oacc[et][0] * inv0, oacc[et][1] * inv0);
        *reinterpret_cast<float2*>(d1 + c0) =
            make_float2(oacc[et][2] * inv1, oacc[et][3] * inv1);
    }
}

// ---------------------------------------------------------------------------
// Kernel 3: residual + LayerNorm. One CTA (256 thr) per (b,s) row, D=1024.
// ---------------------------------------------------------------------------
__global__ __launch_bounds__(256) void ln_res_kernel(
    const float* __restrict__ x,
    const float* __restrict__ gamma,
    const float* __restrict__ beta,
    float* __restrict__ out)
{
    const int row = blockIdx.x;
    const int tid = threadIdx.x;

    float4 ov = reinterpret_cast<const float4*>(g_O + (size_t)row * D_)[tid];
    float4 xv = reinterpret_cast<const float4*>(x   + (size_t)row * D_)[tid];
    float4 y;
    y.x = ov.x + xv.x; y.y = ov.y + xv.y; y.z = ov.z + xv.z; y.w = ov.w + xv.w;

    float s  = y.x + y.y + y.z + y.w;
    float ss = y.x * y.x + y.y * y.y + y.z * y.z + y.w * y.w;
    #pragma unroll
    for (int off = 16; off; off >>= 1) {
        s  += __shfl_xor_sync(0xffffffffu, s,  off);
        ss += __shfl_xor_sync(0xffffffffu, ss, off);
    }

    __shared__ float red[16];
    __shared__ float mu_s, rs_s;
    const int wid = tid >> 5;
    if ((tid & 31) == 0) { red[wid] = s; red[wid + 8] = ss; }
    __syncthreads();
    if (tid == 0) {
        float S = 0.f, SS = 0.f;
        #pragma unroll
        for (int i = 0; i < 8; ++i) { S += red[i]; SS += red[i + 8]; }
        float mu  = S * (1.0f / D_);
        float var = SS * (1.0f / D_) - mu * mu;
        mu_s = mu;
        rs_s = rsqrtf(var + 1e-5f);
    }
    __syncthreads();

    const float mu = mu_s, rstd = rs_s;
    float4 gv = reinterpret_cast<const float4*>(gamma)[tid];
    float4 bv = reinterpret_cast<const float4*>(beta)[tid];
    float4 r;
    r.x = (y.x - mu) * rstd * gv.x + bv.x;
    r.y = (y.y - mu) * rstd * gv.y + bv.y;
    r.z = (y.z - mu) * rstd * gv.z + bv.z;
    r.w = (y.w - mu) * rstd * gv.w + bv.w;
    reinterpret_cast<float4*>(out + (size_t)row * D_)[tid] = r;
}

// ---------------------------------------------------------------------------
extern "C" void kernel_launch(void* const* d_in, const int* in_sizes, int n_in,
                              void* d_out, int out_size)
{
    const float* x     = (const float*)d_in[0];
    const float* Wq    = (const float*)d_in[1];
    const float* bq    = (const float*)d_in[2];
    const float* Wk    = (const float*)d_in[3];
    const float* bk    = (const float*)d_in[4];
    const float* Wv    = (const float*)d_in[5];
    const float* bv    = (const float*)d_in[6];
    const float* gamma = (const float*)d_in[7];
    const float* beta  = (const float*)d_in[8];
    float* out = (float*)d_out;

    const int QKV_SMEM = (128 * XS_ + 3 * 64 * WS_) * (int)sizeof(float);
    cudaFuncSetAttribute(qkv_proj_kernel,
                         cudaFuncAttributeMaxDynamicSharedMemorySize, QKV_SMEM);
    cudaFuncSetAttribute(attn_kernel,
                         cudaFuncAttributeMaxDynamicSharedMemorySize, ATTN_SMEM);

    qkv_proj_kernel<<<dim3((B_ * S_) / 128, H_), 256, QKV_SMEM>>>(
        x, Wq, bq, Wk, bk, Wv, bv);
    attn_kernel<<<dim3(S_ / 128, BH_), 256, ATTN_SMEM>>>();
    ln_res_kernel<<<B_ * S_, 256>>>(x, gamma, beta, out);
}

// round 6
// speedup vs baseline: 6.6171x; 1.8901x over previous
#include <cuda_runtime.h>
#include <cuda_fp16.h>
#include <cstdint>
#include <cstddef>

#define B_  4
#define S_  2048
#define D_  1024
#define H_  16
#define DK_ 64
#define BH_ (B_ * H_)

// Scratch (allocation-free rule: __device__ globals). 16MB each.
__device__ __half g_Qh[BH_ * S_ * DK_];        // pre-scaled by log2(e)/sqrt(dk)
__device__ __half g_Kh[BH_ * S_ * DK_];
__device__ __half g_Vt[BH_ * DK_ * S_];        // [bh][feat][key]
__device__ float  g_O [B_ * S_ * D_];

// ---------------------------------------------------------------------------
// helpers
// ---------------------------------------------------------------------------
__device__ __forceinline__ uint32_t packh(float lo, float hi) {
    uint32_t r;
    asm("cvt.rn.f16x2.f32 %0, %1, %2;" : "=r"(r) : "f"(hi), "f"(lo));
    return r;
}
__device__ __forceinline__ void mma_f16(float* c,
                                        uint32_t a0, uint32_t a1,
                                        uint32_t a2, uint32_t a3,
                                        uint32_t b0, uint32_t b1) {
    asm volatile(
        "mma.sync.aligned.m16n8k16.row.col.f32.f16.f16.f32 "
        "{%0,%1,%2,%3}, {%4,%5,%6,%7}, {%8,%9}, {%0,%1,%2,%3};"
        : "+f"(c[0]), "+f"(c[1]), "+f"(c[2]), "+f"(c[3])
        : "r"(a0), "r"(a1), "r"(a2), "r"(a3), "r"(b0), "r"(b1));
}
#define LDMX4(r0, r1, r2, r3, a) \
    asm volatile("ldmatrix.sync.aligned.m8n8.x4.shared.b16 {%0,%1,%2,%3}, [%4];" \
                 : "=r"(r0), "=r"(r1), "=r"(r2), "=r"(r3) : "r"(a))
#define LDMX4T(r0, r1, r2, r3, a) \
    asm volatile("ldmatrix.sync.aligned.m8n8.x4.trans.shared.b16 {%0,%1,%2,%3}, [%4];" \
                 : "=r"(r0), "=r"(r1), "=r"(r2), "=r"(r3) : "r"(a))
__device__ __forceinline__ float ex2(float x) {
    float y; asm("ex2.approx.ftz.f32 %0, %1;" : "=f"(y) : "f"(x)); return y;
}
__device__ __forceinline__ uint32_t sptr(const void* p) {
    return (uint32_t)__cvta_generic_to_shared(p);
}
#define CP16(dst_u32, src_ptr) \
    asm volatile("cp.async.cg.shared.global [%0], [%1], 16;" \
                 :: "r"(dst_u32), "l"(src_ptr))
#define CP_COMMIT() asm volatile("cp.async.commit_group;")
#define CP_WAIT0()  asm volatile("cp.async.wait_group 0;" ::: "memory")

// ---------------------------------------------------------------------------
// Kernel 1: QKV projection, all-fp16 mma (m16n8k16) + ldmatrix.
// Grid (BS/64, H), 128 threads (4 warps x 16 rows). 32KB static smem.
// x tile [64][64] fp16 SW128; W [k][n] fp16 SW128 (B-frags via ldmatrix.trans).
// ---------------------------------------------------------------------------
__global__ __launch_bounds__(128) void qkv_proj_kernel(
    const float* __restrict__ x,
    const float* __restrict__ Wq, const float* __restrict__ bq,
    const float* __restrict__ Wk, const float* __restrict__ bk,
    const float* __restrict__ Wv, const float* __restrict__ bv)
{
    __shared__ __align__(1024) char xs[64 * 128];
    __shared__ __align__(1024) char ws[3][64 * 128];

    const int h   = blockIdx.y;
    const int m0  = blockIdx.x * 64;
    const int tid = threadIdx.x;

    // Stage x tile: 512 chunks of 8 fp32 -> 16B fp16, SW128.
    #pragma unroll
    for (int n = 0; n < 4; ++n) {
        int i = tid + 128 * n;
        int r = i >> 3, c = i & 7;
        const float4* src = reinterpret_cast<const float4*>(
            x + (size_t)(m0 + r) * D_ + h * DK_ + c * 8);
        float4 f0 = src[0], f1 = src[1];
        uint4 u;
        u.x = packh(f0.x, f0.y); u.y = packh(f0.z, f0.w);
        u.z = packh(f1.x, f1.y); u.w = packh(f1.z, f1.w);
        *reinterpret_cast<uint4*>(xs + r * 128 + ((c * 16) ^ ((r & 7) * 16))) = u;
    }
    // Stage W (3 matrices), same chunking; gmem rows are k (d), cols n (e).
    const float* Wsrc[3] = {Wq, Wk, Wv};
    #pragma unroll
    for (int p = 0; p < 3; ++p) {
        const float* wsrc = Wsrc[p] + h * DK_ * DK_;
        #pragma unroll
        for (int n = 0; n < 4; ++n) {
            int i = tid + 128 * n;
            int r = i >> 3, c = i & 7;
            const float4* src = reinterpret_cast<const float4*>(wsrc + r * 64 + c * 8);
            float4 f0 = src[0], f1 = src[1];
            uint4 u;
            u.x = packh(f0.x, f0.y); u.y = packh(f0.z, f0.w);
            u.z = packh(f1.x, f1.y); u.w = packh(f1.z, f1.w);
            *reinterpret_cast<uint4*>(ws[p] + r * 128 + ((c * 16) ^ ((r & 7) * 16))) = u;
        }
    }
    __syncthreads();

    const int lane = tid & 31, warp = tid >> 5;
    const int g = lane >> 2, t = lane & 3;
    const int rr = lane & 7, qq = lane >> 3;
    const int r0 = warp * 16 + g, r1 = r0 + 8;

    // A fragments from x (ldmatrix x4 per k16 step).
    uint32_t qa[4][4];
    {
        const uint32_t xb = sptr(xs);
        #pragma unroll
        for (int kt = 0; kt < 4; ++kt) {
            uint32_t addr = xb + (warp * 16 + rr + (qq & 1) * 8) * 128
                          + ((kt * 32 + (qq >> 1) * 16) ^ (rr * 16));
            LDMX4(qa[kt][0], qa[kt][1], qa[kt][2], qa[kt][3], addr);
        }
    }

    const float* Bs[3] = {bq, bk, bv};
    const int b  = m0 >> 11;
    const int s0 = m0 & (S_ - 1);
    const int bh = b * H_ + h;
    const float SCL = 0.18033688011112042f;   // log2(e)/sqrt(DK)

    #pragma unroll
    for (int p = 0; p < 3; ++p) {
        const uint32_t wb = sptr(ws[p]);
        float acc[8][4];
        #pragma unroll
        for (int nt = 0; nt < 8; ++nt)
            #pragma unroll
            for (int q = 0; q < 4; ++q) acc[nt][q] = 0.f;

        #pragma unroll
        for (int nt = 0; nt < 8; ++nt) {
            // trans tiles: rows = k (8q + rr), cols = n block nt
            uint32_t a1 = wb + (8 * qq + rr) * 128 + ((nt * 16) ^ (rr * 16));
            uint32_t w0, w1, w2, w3, w4, w5, w6, w7;
            LDMX4T(w0, w1, w2, w3, a1);
            LDMX4T(w4, w5, w6, w7, a1 + 32 * 128);
            mma_f16(acc[nt], qa[0][0], qa[0][1], qa[0][2], qa[0][3], w0, w1);
            mma_f16(acc[nt], qa[1][0], qa[1][1], qa[1][2], qa[1][3], w2, w3);
            mma_f16(acc[nt], qa[2][0], qa[2][1], qa[2][2], qa[2][3], w4, w5);
            mma_f16(acc[nt], qa[3][0], qa[3][1], qa[3][2], qa[3][3], w6, w7);
        }

        const float* bias = Bs[p] + h * DK_;
        if (p == 0) {
            __half* dst = g_Qh + ((size_t)bh * S_ + s0) * DK_;
            #pragma unroll
            for (int nt = 0; nt < 8; ++nt) {
                const int c0 = nt * 8 + 2 * t;
                float bx = bias[c0], by = bias[c0 + 1];
                *reinterpret_cast<uint32_t*>(dst + (size_t)r0 * DK_ + c0) =
                    packh((acc[nt][0] + bx) * SCL, (acc[nt][1] + by) * SCL);
                *reinterpret_cast<uint32_t*>(dst + (size_t)r1 * DK_ + c0) =
                    packh((acc[nt][2] + bx) * SCL, (acc[nt][3] + by) * SCL);
            }
        } else if (p == 1) {
            __half* dst = g_Kh + ((size_t)bh * S_ + s0) * DK_;
            #pragma unroll
            for (int nt = 0; nt < 8; ++nt) {
                const int c0 = nt * 8 + 2 * t;
                float bx = bias[c0], by = bias[c0 + 1];
                *reinterpret_cast<uint32_t*>(dst + (size_t)r0 * DK_ + c0) =
                    packh(acc[nt][0] + bx, acc[nt][1] + by);
                *reinterpret_cast<uint32_t*>(dst + (size_t)r1 * DK_ + c0) =
                    packh(acc[nt][2] + bx, acc[nt][3] + by);
            }
        } else {
            #pragma unroll
            for (int nt = 0; nt < 8; ++nt) {
                const int c0 = nt * 8 + 2 * t;
                float bx = bias[c0], by = bias[c0 + 1];
                g_Vt[((size_t)bh * DK_ + c0)     * S_ + s0 + r0] = __float2half(acc[nt][0] + bx);
                g_Vt[((size_t)bh * DK_ + c0 + 1) * S_ + s0 + r0] = __float2half(acc[nt][1] + by);
                g_Vt[((size_t)bh * DK_ + c0)     * S_ + s0 + r1] = __float2half(acc[nt][2] + bx);
                g_Vt[((size_t)bh * DK_ + c0 + 1) * S_ + s0 + r1] = __float2half(acc[nt][3] + by);
            }
        }
    }
}

// ---------------------------------------------------------------------------
// Kernel 2: fp16 flash attention, BM=128, BN=64, 256 threads (8 warps).
// QK + PV both m16n8k16 fp16; operands via ldmatrix.x4 from SW128 tiles.
// K/V double-buffered cp.async; ONE __syncthreads per kv-tile.
// ---------------------------------------------------------------------------
__device__ __forceinline__ void stage_tile(uint32_t dst, const __half* src,
                                           int src_stride, int tid) {
    // 64 rows x 128B, SW128 swizzle; 512 chunks, 2 per thread (256 thr).
    #pragma unroll
    for (int n = 0; n < 2; ++n) {
        int i = tid + 256 * n;
        int r = i >> 3, c = i & 7;
        CP16(dst + r * 128 + ((c * 16) ^ ((r & 7) * 16)),
             src + (size_t)r * src_stride + c * 8);
    }
}

__global__ __launch_bounds__(256, 2) void attn_kernel()
{
    __shared__ __align__(1024) char sk[2][64 * 128];
    __shared__ __align__(1024) char sv[2][64 * 128];

    const int it   = (gridDim.x - 1) - blockIdx.x;   // heavy tiles first
    const int bh   = blockIdx.y;
    const int tid  = threadIdx.x;
    const int lane = tid & 31, warp = tid >> 5;
    const int g    = lane >> 2, t = lane & 3;
    const int rr   = lane & 7,  qq = lane >> 3;
    const int r0   = warp * 16 + g, r1 = r0 + 8;

    const __half* Kb = g_Kh + (size_t)bh * S_ * DK_;
    const __half* Vb = g_Vt + (size_t)bh * DK_ * S_;

    // Stage kv-tile 0.
    stage_tile(sptr(sk[0]), Kb, DK_, tid);
    stage_tile(sptr(sv[0]), Vb, S_, tid);
    CP_COMMIT();

    // Q A-fragments straight from gmem (pre-scaled fp16).
    const __half* Qp = g_Qh + ((size_t)bh * S_ + it * 128) * DK_;
    uint32_t qf[4][4];
    #pragma unroll
    for (int kt = 0; kt < 4; ++kt) {
        qf[kt][0] = *reinterpret_cast<const uint32_t*>(Qp + (size_t)r0 * DK_ + 16 * kt + 2 * t);
        qf[kt][1] = *reinterpret_cast<const uint32_t*>(Qp + (size_t)r1 * DK_ + 16 * kt + 2 * t);
        qf[kt][2] = *reinterpret_cast<const uint32_t*>(Qp + (size_t)r0 * DK_ + 16 * kt + 2 * t + 8);
        qf[kt][3] = *reinterpret_cast<const uint32_t*>(Qp + (size_t)r1 * DK_ + 16 * kt + 2 * t + 8);
    }

    // per-thread ldmatrix offsets (nt-independent parts)
    const uint32_t offA = rr * 128 + ((qq * 16) ^ (rr * 16));
    const uint32_t offB = rr * 128 + (((64 + qq * 16)) ^ (rr * 16));

    float m0 = -1e30f, m1 = -1e30f, l0 = 0.f, l1 = 0.f;
    float oacc[8][4];
    #pragma unroll
    for (int et = 0; et < 8; ++et)
        #pragma unroll
        for (int q = 0; q < 4; ++q) oacc[et][q] = 0.f;

    const int jtmax = 2 * it + 1;

    for (int jt = 0; jt <= jtmax; ++jt) {
        CP_WAIT0();
        __syncthreads();       // tile jt staged & all warps done with jt-1

        const int cur = jt & 1;
        if (jt < jtmax) {      // prefetch jt+1 into the other buffer
            stage_tile(sptr(sk[cur ^ 1]), Kb + (size_t)(jt + 1) * 64 * DK_, DK_, tid);
            stage_tile(sptr(sv[cur ^ 1]), Vb + (jt + 1) * 64, S_, tid);
            CP_COMMIT();
        }

        // warps 0-3 (rows < 64) are fully masked on the 2nd diagonal tile
        if (warp < 4 && jt == jtmax && it >= 0 && jt == 2 * it + 1) {
            // nothing to compute for this warp on this tile
            continue;
        }

        const uint32_t kbase = sptr(sk[cur]);
        const uint32_t vbase = sptr(sv[cur]);

        // ---- S = Q K^T ----
        float sacc[8][4];
        #pragma unroll
        for (int nt = 0; nt < 8; ++nt) {
            uint32_t k0, k1, k2, k3, k4, k5, k6, k7;
            LDMX4(k0, k1, k2, k3, kbase + nt * 1024 + offA);
            LDMX4(k4, k5, k6, k7, kbase + nt * 1024 + offB);
            #pragma unroll
            for (int q = 0; q < 4; ++q) sacc[nt][q] = 0.f;
            mma_f16(sacc[nt], qf[0][0], qf[0][1], qf[0][2], qf[0][3], k0, k1);
            mma_f16(sacc[nt], qf[1][0], qf[1][1], qf[1][2], qf[1][3], k2, k3);
            mma_f16(sacc[nt], qf[2][0], qf[2][1], qf[2][2], qf[2][3], k4, k5);
            mma_f16(sacc[nt], qf[3][0], qf[3][1], qf[3][2], qf[3][3], k6, k7);
        }

        // ---- online softmax (scores already in log2 domain via pre-scaled Q)
        const bool diag = (jt >= 2 * it);
        const int  coff = (jt - 2 * it) * 64;
        float rm0 = -1e30f, rm1 = -1e30f;
        #pragma unroll
        for (int nt = 0; nt < 8; ++nt) {
            const int c0 = nt * 8 + 2 * t;
            float v00 = sacc[nt][0], v01 = sacc[nt][1];
            float v10 = sacc[nt][2], v11 = sacc[nt][3];
            if (diag) {
                if (c0 + coff     > r0) v00 = -1e30f;
                if (c0 + 1 + coff > r0) v01 = -1e30f;
                if (c0 + coff     > r1) v10 = -1e30f;
                if (c0 + 1 + coff > r1) v11 = -1e30f;
            }
            sacc[nt][0] = v00; sacc[nt][1] = v01;
            sacc[nt][2] = v10; sacc[nt][3] = v11;
            rm0 = fmaxf(rm0, fmaxf(v00, v01));
            rm1 = fmaxf(rm1, fmaxf(v10, v11));
        }
        rm0 = fmaxf(rm0, __shfl_xor_sync(0xffffffffu, rm0, 1));
        rm0 = fmaxf(rm0, __shfl_xor_sync(0xffffffffu, rm0, 2));
        rm1 = fmaxf(rm1, __shfl_xor_sync(0xffffffffu, rm1, 1));
        rm1 = fmaxf(rm1, __shfl_xor_sync(0xffffffffu, rm1, 2));

        const float mn0 = fmaxf(m0, rm0), mn1 = fmaxf(m1, rm1);
        const float al0 = ex2(m0 - mn0), al1 = ex2(m1 - mn1);
        m0 = mn0; m1 = mn1;

        float rs0 = 0.f, rs1 = 0.f;
        #pragma unroll
        for (int nt = 0; nt < 8; ++nt) {
            float p00 = ex2(sacc[nt][0] - mn0);
            float p01 = ex2(sacc[nt][1] - mn0);
            float p10 = ex2(sacc[nt][2] - mn1);
            float p11 = ex2(sacc[nt][3] - mn1);
            sacc[nt][0] = p00; sacc[nt][1] = p01;
            sacc[nt][2] = p10; sacc[nt][3] = p11;
            rs0 += p00 + p01;
            rs1 += p10 + p11;
        }
        rs0 += __shfl_xor_sync(0xffffffffu, rs0, 1);
        rs0 += __shfl_xor_sync(0xffffffffu, rs0, 2);
        rs1 += __shfl_xor_sync(0xffffffffu, rs1, 1);
        rs1 += __shfl_xor_sync(0xffffffffu, rs1, 2);
        l0 = l0 * al0 + rs0;
        l1 = l1 * al1 + rs1;
        #pragma unroll
        for (int et = 0; et < 8; ++et) {
            oacc[et][0] *= al0; oacc[et][1] *= al0;
            oacc[et][2] *= al1; oacc[et][3] *= al1;
        }

        // ---- pack P into fp16 A-fragments (pure registers) ----
        uint32_t pa[4][4];
        #pragma unroll
        for (int kt = 0; kt < 4; ++kt) {
            pa[kt][0] = packh(sacc[2 * kt][0],     sacc[2 * kt][1]);
            pa[kt][1] = packh(sacc[2 * kt][2],     sacc[2 * kt][3]);
            pa[kt][2] = packh(sacc[2 * kt + 1][0], sacc[2 * kt + 1][1]);
            pa[kt][3] = packh(sacc[2 * kt + 1][2], sacc[2 * kt + 1][3]);
        }

        // ---- O += P V ----
        #pragma unroll
        for (int nt = 0; nt < 8; ++nt) {
            uint32_t v0, v1, v2, v3, v4, v5, v6, v7;
            LDMX4(v0, v1, v2, v3, vbase + nt * 1024 + offA);
            LDMX4(v4, v5, v6, v7, vbase + nt * 1024 + offB);
            mma_f16(oacc[nt], pa[0][0], pa[0][1], pa[0][2], pa[0][3], v0, v1);
            mma_f16(oacc[nt], pa[1][0], pa[1][1], pa[1][2], pa[1][3], v2, v3);
            mma_f16(oacc[nt], pa[2][0], pa[2][1], pa[2][2], pa[2][3], v4, v5);
            mma_f16(oacc[nt], pa[3][0], pa[3][1], pa[3][2], pa[3][3], v6, v7);
        }
    }

    // Epilogue: normalize, write O in [B,S,D] layout.
    const int b = bh >> 4, h = bh & 15;
    const float inv0 = 1.0f / l0, inv1 = 1.0f / l1;
    float* d0 = g_O + (size_t)(b * S_ + it * 128 + r0) * D_ + h * DK_;
    float* d1 = g_O + (size_t)(b * S_ + it * 128 + r1) * D_ + h * DK_;
    #pragma unroll
    for (int et = 0; et < 8; ++et) {
        const int c0 = et * 8 + 2 * t;
        *reinterpret_cast<float2*>(d0 + c0) =
            make_float2(oacc[et][0] * inv0, oacc[et][1] * inv0);
        *reinterpret_cast<float2*>(d1 + c0) =
            make_float2(oacc[et][2] * inv1, oacc[et][3] * inv1);
    }
}

// ---------------------------------------------------------------------------
// Kernel 3: residual + LayerNorm. One CTA (256 thr) per (b,s) row, D=1024.
// ---------------------------------------------------------------------------
__global__ __launch_bounds__(256) void ln_res_kernel(
    const float* __restrict__ x,
    const float* __restrict__ gamma,
    const float* __restrict__ beta,
    float* __restrict__ out)
{
    const int row = blockIdx.x;
    const int tid = threadIdx.x;

    float4 ov = reinterpret_cast<const float4*>(g_O + (size_t)row * D_)[tid];
    float4 xv = reinterpret_cast<const float4*>(x   + (size_t)row * D_)[tid];
    float4 y;
    y.x = ov.x + xv.x; y.y = ov.y + xv.y; y.z = ov.z + xv.z; y.w = ov.w + xv.w;

    float s  = y.x + y.y + y.z + y.w;
    float ss = y.x * y.x + y.y * y.y + y.z * y.z + y.w * y.w;
    #pragma unroll
    for (int off = 16; off; off >>= 1) {
        s  += __shfl_xor_sync(0xffffffffu, s,  off);
        ss += __shfl_xor_sync(0xffffffffu, ss, off);
    }

    __shared__ float red[16];
    __shared__ float mu_s, rs_s;
    const int wid = tid >> 5;
    if ((tid & 31) == 0) { red[wid] = s; red[wid + 8] = ss; }
    __syncthreads();
    if (tid == 0) {
        float S = 0.f, SS = 0.f;
        #pragma unroll
        for (int i = 0; i < 8; ++i) { S += red[i]; SS += red[i + 8]; }
        float mu  = S * (1.0f / D_);
        float var = SS * (1.0f / D_) - mu * mu;
        mu_s = mu;
        rs_s = rsqrtf(var + 1e-5f);
    }
    __syncthreads();

    const float mu = mu_s, rstd = rs_s;
    float4 gv = reinterpret_cast<const float4*>(gamma)[tid];
    float4 bv = reinterpret_cast<const float4*>(beta)[tid];
    float4 r;
    r.x = (y.x - mu) * rstd * gv.x + bv.x;
    r.y = (y.y - mu) * rstd * gv.y + bv.y;
    r.z = (y.z - mu) * rstd * gv.z + bv.z;
    r.w = (y.w - mu) * rstd * gv.w + bv.w;
    reinterpret_cast<float4*>(out + (size_t)row * D_)[tid] = r;
}

// ---------------------------------------------------------------------------
extern "C" void kernel_launch(void* const* d_in, const int* in_sizes, int n_in,
                              void* d_out, int out_size)
{
    const float* x     = (const float*)d_in[0];
    const float* Wq    = (const float*)d_in[1];
    const float* bq    = (const float*)d_in[2];
    const float* Wk    = (const float*)d_in[3];
    const float* bk    = (const float*)d_in[4];
    const float* Wv    = (const float*)d_in[5];
    const float* bv    = (const float*)d_in[6];
    const float* gamma = (const float*)d_in[7];
    const float* beta  = (const float*)d_in[8];
    float* out = (float*)d_out;

    qkv_proj_kernel<<<dim3((B_ * S_) / 64, H_), 128>>>(x, Wq, bq, Wk, bk, Wv, bv);
    attn_kernel<<<dim3(S_ / 128, BH_), 256>>>();
    ln_res_kernel<<<B_ * S_, 256>>>(x, gamma, beta, out);
}